// round 1
// baseline (speedup 1.0000x reference)
#include <cuda_runtime.h>
#include <cstdint>

// ---- problem constants (fixed by the dataset) ----
#define NND   16384      // nodes = B*S*NN
#define EDG   262144     // edges
#define DD    128        // hidden dim
#define SS    128        // seq len
#define NNPG  64         // nodes per graph-step
#define LL    6          // layers

// ---- scratch (device globals; no allocation allowed) ----
__device__ float g_h[NND * DD];                 // 8 MB   hidden state
__device__ float g_qkvs[(size_t)NND * 4 * DD];  // 32 MB  q|k|v|xr per node
__device__ int   g_deg[NND];
__device__ int   g_off[NND + 1];
__device__ int   g_cur[NND];
__device__ int   g_csr[EDG];                    // src id per CSR slot (grouped by dst)

// =====================================================================
// CSR build
// =====================================================================
__global__ void k_zero_deg() {
    int i = blockIdx.x * blockDim.x + threadIdx.x;
    if (i < NND) g_deg[i] = 0;
}

__global__ void k_count(const int* __restrict__ dst) {
    int e = blockIdx.x * blockDim.x + threadIdx.x;
    if (e < EDG) atomicAdd(&g_deg[dst[e]], 1);
}

__global__ void k_scan() {
    // 512 threads, each owns 32 consecutive nodes; Hillis-Steele on partials.
    __shared__ int part[512];
    int t = threadIdx.x;
    int base = t * 32;
    int s = 0;
#pragma unroll
    for (int i = 0; i < 32; i++) s += g_deg[base + i];
    part[t] = s;
    __syncthreads();
    for (int ofs = 1; ofs < 512; ofs <<= 1) {
        int v = (t >= ofs) ? part[t - ofs] : 0;
        __syncthreads();
        part[t] += v;
        __syncthreads();
    }
    int run = (t == 0) ? 0 : part[t - 1];
#pragma unroll
    for (int i = 0; i < 32; i++) {
        g_off[base + i] = run;
        g_cur[base + i] = run;
        run += g_deg[base + i];
    }
    if (t == 511) g_off[NND] = part[511];
}

__global__ void k_fill(const int* __restrict__ src, const int* __restrict__ dst) {
    int e = blockIdx.x * blockDim.x + threadIdx.x;
    if (e < EDG) {
        int d = dst[e];
        int p = atomicAdd(&g_cur[d], 1);
        g_csr[p] = src[e];
    }
}

// =====================================================================
// Input projection + positional encoding: h = x @ Win + bin + pe[s]
// =====================================================================
__global__ void k_input(const float* __restrict__ x, const float* __restrict__ Win,
                        const float* __restrict__ bin, const float* __restrict__ pe) {
    int idx = blockIdx.x * blockDim.x + threadIdx.x;
    if (idx >= NND * DD) return;
    int n = idx >> 7;
    int d = idx & 127;
    int s = (n / NNPG) % SS;
    float acc = bin[d] + pe[s * DD + d];
    const float* xr = x + n * 9;
#pragma unroll
    for (int f = 0; f < 9; f++) acc = fmaf(xr[f], Win[f * DD + d], acc);
    g_h[idx] = acc;
}

// =====================================================================
// Fused QKVS GEMM: qkvs[n, m*128+c] = h @ W_m + b_m for m in {q,k,v,s}
// Tile: 128 rows x 64 cols, BK=32, 256 threads, micro 8x4 using fma.rn.f32x2
// =====================================================================
__device__ __forceinline__ unsigned long long f2dup(float v) {
    unsigned long long r;
    asm("mov.b64 %0, {%1, %1};" : "=l"(r) : "f"(v));
    return r;
}

__global__ __launch_bounds__(256) void k_gemm(
    const float* __restrict__ Wq, const float* __restrict__ Wk,
    const float* __restrict__ Wv, const float* __restrict__ Ws,
    const float* __restrict__ bq, const float* __restrict__ bk,
    const float* __restrict__ bv, const float* __restrict__ bs)
{
    __shared__ float As[32][132];   // A tile transposed (k-major), padded
    __shared__ float Bs[32][64];

    int by   = blockIdx.y;                 // 0..7
    int row0 = blockIdx.x * 128;
    int mat  = by >> 1;                    // 0:q 1:k 2:v 3:xr
    const float* W    = (mat == 0) ? Wq : (mat == 1) ? Wk : (mat == 2) ? Wv : Ws;
    const float* bias = (mat == 0) ? bq : (mat == 1) ? bk : (mat == 2) ? bv : bs;
    int wc0 = (by & 1) * 64;

    int tid = threadIdx.x;
    int tx = tid & 15, ty = tid >> 4;
    int c0 = tx * 4, m0 = ty * 8;

    unsigned long long acc[4][4];
#pragma unroll
    for (int i = 0; i < 4; i++)
#pragma unroll
        for (int j = 0; j < 4; j++) acc[i][j] = 0ull;

    for (int k0 = 0; k0 < 128; k0 += 32) {
        // load A tile (transposed into smem)
#pragma unroll
        for (int i = 0; i < 4; i++) {
            int f4 = tid + i * 256;            // 0..1023
            int m = f4 >> 3, kq = f4 & 7;
            float4 v = *(const float4*)&g_h[(size_t)(row0 + m) * DD + k0 + kq * 4];
            As[kq * 4 + 0][m] = v.x;
            As[kq * 4 + 1][m] = v.y;
            As[kq * 4 + 2][m] = v.z;
            As[kq * 4 + 3][m] = v.w;
        }
        // load B tile
#pragma unroll
        for (int i = 0; i < 2; i++) {
            int f4 = tid + i * 256;            // 0..511
            int k = f4 >> 4, cq = f4 & 15;
            *(float4*)&Bs[k][cq * 4] =
                *(const float4*)&W[(size_t)(k0 + k) * DD + wc0 + cq * 4];
        }
        __syncthreads();

#pragma unroll
        for (int kk = 0; kk < 32; kk++) {
            unsigned long long a[4];
            a[0] = *(const unsigned long long*)&As[kk][m0 + 0];
            a[1] = *(const unsigned long long*)&As[kk][m0 + 2];
            a[2] = *(const unsigned long long*)&As[kk][m0 + 4];
            a[3] = *(const unsigned long long*)&As[kk][m0 + 6];
            float4 b = *(const float4*)&Bs[kk][c0];
            unsigned long long bd[4];
            bd[0] = f2dup(b.x); bd[1] = f2dup(b.y);
            bd[2] = f2dup(b.z); bd[3] = f2dup(b.w);
#pragma unroll
            for (int i = 0; i < 4; i++)
#pragma unroll
                for (int j = 0; j < 4; j++)
                    asm("fma.rn.f32x2 %0, %1, %2, %0;"
                        : "+l"(acc[i][j]) : "l"(a[i]), "l"(bd[j]));
        }
        __syncthreads();
    }

    // epilogue: unpack, add bias, store
#pragma unroll
    for (int j = 0; j < 4; j++) {
        int c = c0 + j;
        float bv_ = bias[wc0 + c];
#pragma unroll
        for (int i = 0; i < 4; i++) {
            float lo, hi;
            asm("mov.b64 {%0, %1}, %2;" : "=f"(lo), "=f"(hi) : "l"(acc[i][j]));
            int m = m0 + i * 2;
            g_qkvs[(size_t)(row0 + m)     * 512 + mat * 128 + wc0 + c] = lo + bv_;
            g_qkvs[(size_t)(row0 + m + 1) * 512 + mat * 128 + wc0 + c] = hi + bv_;
        }
    }
}

// =====================================================================
// Fused attention: one warp per dst node.
// online softmax over incoming edges -> agg, then beta-gate + residual + LN
// lane layout: lane = head*4 + quarter; each lane owns dims [lane*4, lane*4+4)
// =====================================================================
__global__ __launch_bounds__(256) void k_attn(
    const float* __restrict__ Wb, const float* __restrict__ bb,
    const float* __restrict__ lng, const float* __restrict__ lnb)
{
    int gw = (blockIdx.x * 256 + threadIdx.x) >> 5;   // node id
    if (gw >= NND) return;
    int lane = threadIdx.x & 31;

    float4 q = ((const float4*)(g_qkvs + (size_t)gw * 512))[lane];
    q.x *= 0.25f; q.y *= 0.25f; q.z *= 0.25f; q.w *= 0.25f;  // 1/sqrt(C), C=16

    float m = __int_as_float(0xff800000);  // -inf
    float den = 0.f;
    float4 acc = make_float4(0.f, 0.f, 0.f, 0.f);

    int beg = g_off[gw], end = g_off[gw + 1];
    for (int e = beg; e < end; e++) {
        int s = g_csr[e];
        const float* base = g_qkvs + (size_t)s * 512;
        float4 kf = ((const float4*)(base + 128))[lane];
        float4 vf = ((const float4*)(base + 256))[lane];
        float sc = q.x * kf.x + q.y * kf.y + q.z * kf.z + q.w * kf.w;
        sc += __shfl_xor_sync(0xffffffffu, sc, 1);
        sc += __shfl_xor_sync(0xffffffffu, sc, 2);   // full per-head score
        float mn  = fmaxf(m, sc);
        float scl = __expf(m - mn);
        float p   = __expf(sc - mn);
        acc.x = acc.x * scl + p * vf.x;
        acc.y = acc.y * scl + p * vf.y;
        acc.z = acc.z * scl + p * vf.z;
        acc.w = acc.w * scl + p * vf.w;
        den = den * scl + p;
        m = mn;
    }
    float inv = 1.f / (den + 1e-16f);
    float ag[4] = {acc.x * inv, acc.y * inv, acc.z * inv, acc.w * inv};

    // beta gate: sigmoid([agg, xr, agg-xr] @ Wb + bb)
    float4 xr = ((const float4*)(g_qkvs + (size_t)gw * 512 + 384))[lane];
    float xrv[4] = {xr.x, xr.y, xr.z, xr.w};
    int d0 = lane * 4;
    float part = 0.f;
#pragma unroll
    for (int j = 0; j < 4; j++) {
        int d = d0 + j;
        part += ag[j] * Wb[d] + xrv[j] * Wb[128 + d] + (ag[j] - xrv[j]) * Wb[256 + d];
    }
#pragma unroll
    for (int o = 16; o; o >>= 1) part += __shfl_xor_sync(0xffffffffu, part, o);
    float z = part + bb[0];
    float beta = 1.f / (1.f + __expf(-z));

    // hn = beta*xr + (1-beta)*agg ; h = LN(h + hn)
    float4 hold = ((const float4*)(g_h + (size_t)gw * 128))[lane];
    float hv[4] = {hold.x, hold.y, hold.z, hold.w};
    float y[4];
#pragma unroll
    for (int j = 0; j < 4; j++)
        y[j] = hv[j] + beta * xrv[j] + (1.f - beta) * ag[j];

    float ssum = y[0] + y[1] + y[2] + y[3];
#pragma unroll
    for (int o = 16; o; o >>= 1) ssum += __shfl_xor_sync(0xffffffffu, ssum, o);
    float mean = ssum * (1.f / 128.f);

    float vs = 0.f;
#pragma unroll
    for (int j = 0; j < 4; j++) { float t = y[j] - mean; vs += t * t; }
#pragma unroll
    for (int o = 16; o; o >>= 1) vs += __shfl_xor_sync(0xffffffffu, vs, o);
    float rstd = rsqrtf(vs * (1.f / 128.f) + 1e-5f);

    float4 outv;
    outv.x = (y[0] - mean) * rstd * lng[d0 + 0] + lnb[d0 + 0];
    outv.y = (y[1] - mean) * rstd * lng[d0 + 1] + lnb[d0 + 1];
    outv.z = (y[2] - mean) * rstd * lng[d0 + 2] + lnb[d0 + 2];
    outv.w = (y[3] - mean) * rstd * lng[d0 + 3] + lnb[d0 + 3];
    ((float4*)(g_h + (size_t)gw * 128))[lane] = outv;
}

// =====================================================================
// Output head: out = relu(h @ Wo1 + bo1) @ Wo2 + bo2    (16 nodes / block)
// =====================================================================
__global__ __launch_bounds__(256) void k_out(
    const float* __restrict__ Wo1, const float* __restrict__ bo1,
    const float* __restrict__ Wo2, const float* __restrict__ bo2,
    float* __restrict__ out)
{
    __shared__ float w1[128 * 64];   // 32 KB
    __shared__ float hs[16][128];    //  8 KB
    __shared__ float ts[16][64];     //  4 KB
    int tid = threadIdx.x;
    int n0 = blockIdx.x * 16;

    for (int i = tid; i < 128 * 64 / 4; i += 256)
        ((float4*)w1)[i] = ((const float4*)Wo1)[i];
    for (int i = tid; i < 16 * 128 / 4; i += 256)
        ((float4*)&hs[0][0])[i] = ((const float4*)(g_h + (size_t)n0 * 128))[i];
    __syncthreads();

    int j = tid & 63, g0 = tid >> 6;   // 4 nodes per thread
    float a0 = bo1[j], a1 = a0, a2 = a0, a3 = a0;
#pragma unroll 8
    for (int d = 0; d < 128; d++) {
        float w = w1[d * 64 + j];
        a0 = fmaf(hs[g0 +  0][d], w, a0);
        a1 = fmaf(hs[g0 +  4][d], w, a1);
        a2 = fmaf(hs[g0 +  8][d], w, a2);
        a3 = fmaf(hs[g0 + 12][d], w, a3);
    }
    ts[g0 +  0][j] = fmaxf(a0, 0.f);
    ts[g0 +  4][j] = fmaxf(a1, 0.f);
    ts[g0 +  8][j] = fmaxf(a2, 0.f);
    ts[g0 + 12][j] = fmaxf(a3, 0.f);
    __syncthreads();

    if (tid < 48) {
        int n = tid / 3, c = tid % 3;
        float o = bo2[c];
#pragma unroll
        for (int k = 0; k < 64; k++) o = fmaf(ts[n][k], Wo2[k * 3 + c], o);
        out[(size_t)(n0 + n) * 3 + c] = o;
    }
}

// =====================================================================
// launcher
// =====================================================================
extern "C" void kernel_launch(void* const* d_in, const int* in_sizes, int n_in,
                              void* d_out, int out_size)
{
    const float* x    = (const float*)d_in[0];
    const int*   ei   = (const int*)  d_in[1];
    const float* pe   = (const float*)d_in[2];
    const float* Win  = (const float*)d_in[3];
    const float* bin  = (const float*)d_in[4];
    const float* Wq   = (const float*)d_in[5];
    const float* bq   = (const float*)d_in[6];
    const float* Wk   = (const float*)d_in[7];
    const float* bk   = (const float*)d_in[8];
    const float* Wv   = (const float*)d_in[9];
    const float* bv   = (const float*)d_in[10];
    const float* Ws   = (const float*)d_in[11];
    const float* bs   = (const float*)d_in[12];
    const float* Wb   = (const float*)d_in[13];
    const float* bb   = (const float*)d_in[14];
    const float* lng  = (const float*)d_in[15];
    const float* lnb  = (const float*)d_in[16];
    const float* Wo1  = (const float*)d_in[17];
    const float* bo1  = (const float*)d_in[18];
    const float* Wo2  = (const float*)d_in[19];
    const float* bo2  = (const float*)d_in[20];
    float* out = (float*)d_out;

    const int* src = ei;
    const int* dst = ei + EDG;

    // CSR build (runs every replay; deterministic work, ~5us)
    k_zero_deg<<<NND / 256, 256>>>();
    k_count<<<EDG / 256, 256>>>(dst);
    k_scan<<<1, 512>>>();
    k_fill<<<EDG / 256, 256>>>(src, dst);

    // input projection + PE
    k_input<<<NND * DD / 256, 256>>>(x, Win, bin, pe);

    for (int l = 0; l < LL; l++) {
        dim3 gg(NND / 128, 8);
        k_gemm<<<gg, 256>>>(Wq + (size_t)l * DD * DD, Wk + (size_t)l * DD * DD,
                            Wv + (size_t)l * DD * DD, Ws + (size_t)l * DD * DD,
                            bq + l * DD, bk + l * DD, bv + l * DD, bs + l * DD);
        k_attn<<<NND / 8, 256>>>(Wb + l * 384, bb + l, lng + l * DD, lnb + l * DD);
    }

    k_out<<<NND / 16, 256>>>(Wo1, bo1, Wo2, bo2, out);
}